// round 16
// baseline (speedup 1.0000x reference)
#include <cuda_runtime.h>
#include <cuda_bf16.h>
#include <cstdint>

// ============================================================================
// multimodal_attention via mma.sync (HMMA bf16 hi/lo split) on sm_103
// out[b,q,:] = softmax_k(Q.K^T) @ V       B=32, S=2048, D=64, fp32
//
// R15: split-K reverted (neutral).  4 CTAs/SM enabled by:
//   - smem 48KB/CTA: K double-buffered, V SINGLE-buffered (separate cp.async
//     group, waited just before MMA2 -> load hidden under MMA1+exp).
//   - per-half MMA1 restructure (sacc 16 regs) + __launch_bounds__(128,4).
// ============================================================================

#define BATCH 32
#define SEQ   2048
#define DIM   64
#define QT    64             // q rows per CTA
#define KT    64             // keys per tile
#define NTILES (SEQ / KT)    // 32
#define NTHREADS 128

#define KV_ELEMS (BATCH * SEQ * DIM)     // 4,194,304

// preconverted K/V scratch (32 MB total); K pre-scaled by log2(e)
__device__ __nv_bfloat16 g_khi[KV_ELEMS];
__device__ __nv_bfloat16 g_klo[KV_ELEMS];
__device__ __nv_bfloat16 g_vhi[KV_ELEMS];
__device__ __nv_bfloat16 g_vlo[KV_ELEMS];

// smem layout (static 48KB):
//   Kb0 [0,16K)  : {khi 8K, klo 8K} tile buffer 0
//   Kb1 [16K,32K): {khi 8K, klo 8K} tile buffer 1  (also Q staging in prologue)
//   Vb  [32K,48K): {vhi 8K, vlo 8K} single buffer
#define SM_KB0 0
#define SM_KB1 16384
#define SM_VB  32768
#define SMEM_BYTES 49152

__device__ __forceinline__ uint32_t smem_u32(const void* p) {
    uint32_t a;
    asm("{ .reg .u64 t; cvta.to.shared.u64 t, %1; cvt.u32.u64 %0, t; }" : "=r"(a) : "l"(p));
    return a;
}
// 128B rows; xor-swizzle 16B chunks by row&7 -> conflict-free ldmatrix
__device__ __forceinline__ uint32_t swa(int row, int col16) {
    return (uint32_t)(row * 128 + ((col16 ^ (row & 7)) << 4));
}
__device__ __forceinline__ uint32_t packhi(float a, float b) {
    __nv_bfloat162 t = __floats2bfloat162_rn(a, b);
    return *reinterpret_cast<uint32_t*>(&t);
}
__device__ __forceinline__ uint32_t packlo(float a, float b) {
    float ah = __bfloat162float(__float2bfloat16_rn(a));
    float bh = __bfloat162float(__float2bfloat16_rn(b));
    __nv_bfloat162 t = __floats2bfloat162_rn(a - ah, b - bh);
    return *reinterpret_cast<uint32_t*>(&t);
}
__device__ __forceinline__ float ex2f(float x) {
    float r;
    asm("ex2.approx.ftz.f32 %0, %1;" : "=f"(r) : "f"(x));
    return r;
}

#define CP_ASYNC16(SM, GM) \
    asm volatile("cp.async.cg.shared.global [%0], [%1], 16;" :: "r"(SM), "l"(GM) : "memory")
#define CP_COMMIT()  asm volatile("cp.async.commit_group;" ::: "memory")
#define CP_WAITG(N)  asm volatile("cp.async.wait_group %0;" :: "n"(N) : "memory")

#define LDSM_X4(R0,R1,R2,R3,ADDR) \
    asm volatile("ldmatrix.sync.aligned.m8n8.x4.shared.b16 {%0,%1,%2,%3}, [%4];" \
                 : "=r"(R0),"=r"(R1),"=r"(R2),"=r"(R3) : "r"(ADDR))
#define LDSM_X4T(R0,R1,R2,R3,ADDR) \
    asm volatile("ldmatrix.sync.aligned.m8n8.x4.trans.shared.b16 {%0,%1,%2,%3}, [%4];" \
                 : "=r"(R0),"=r"(R1),"=r"(R2),"=r"(R3) : "r"(ADDR))
// D += A * B   (m16n8k16, bf16 in, f32 accum)
#define MMA(D,A,B0,B1) \
    asm volatile("mma.sync.aligned.m16n8k16.row.col.f32.bf16.bf16.f32 " \
                 "{%0,%1,%2,%3},{%4,%5,%6,%7},{%8,%9},{%0,%1,%2,%3};" \
                 : "+f"((D)[0]),"+f"((D)[1]),"+f"((D)[2]),"+f"((D)[3]) \
                 : "r"((A)[0]),"r"((A)[1]),"r"((A)[2]),"r"((A)[3]),"r"(B0),"r"(B1))

// ---------------------------------------------------------------------------
// Pre-pass: K,V fp32 -> bf16 hi/lo scratch.  K scaled by log2(e).
// ---------------------------------------------------------------------------
__global__ __launch_bounds__(256)
void kv_convert_kernel(const float* __restrict__ k, const float* __restrict__ v)
{
    const float LOG2E = 1.4426950408889634f;
    int i = blockIdx.x * 256 + threadIdx.x;          // float4 index
    float4 kx = reinterpret_cast<const float4*>(k)[i];
    kx.x *= LOG2E; kx.y *= LOG2E; kx.z *= LOG2E; kx.w *= LOG2E;
    float4 vx = reinterpret_cast<const float4*>(v)[i];
    reinterpret_cast<uint2*>(g_khi)[i] = make_uint2(packhi(kx.x, kx.y), packhi(kx.z, kx.w));
    reinterpret_cast<uint2*>(g_klo)[i] = make_uint2(packlo(kx.x, kx.y), packlo(kx.z, kx.w));
    reinterpret_cast<uint2*>(g_vhi)[i] = make_uint2(packhi(vx.x, vx.y), packhi(vx.z, vx.w));
    reinterpret_cast<uint2*>(g_vlo)[i] = make_uint2(packlo(vx.x, vx.y), packlo(vx.z, vx.w));
}

// ---------------------------------------------------------------------------
// Attention kernel
// ---------------------------------------------------------------------------
__global__ __launch_bounds__(NTHREADS, 4)
void attn_mma_kernel(const float* __restrict__ q,
                     float* __restrict__ out)
{
    __shared__ __align__(1024) char smem[SMEM_BYTES];
    const uint32_t sb = smem_u32(smem);
    const int tid  = threadIdx.x;
    const int w    = tid >> 5;                // warp 0..3
    const int lane = tid & 31;
    const int b     = blockIdx.y;
    const int qbase = blockIdx.x * QT;
    const int wr0   = w * 16;                 // this warp's q-row base in tile

    const size_t kvbase = (size_t)b * SEQ * DIM;

    // per-thread staging geometry: 4 chunks per array, e = j*128+tid
    // row = e>>3, c16 = e&7; src byte off = row*128 + c16*16 (bf16 row = 128B)
    // dst = arrhalf*8192 + swa(row, c16)

    // ---- prologue group 1: K(0) -> Kb0 ----
    {
        const char* khi_p = (const char*)(g_khi + kvbase);
        const char* klo_p = (const char*)(g_klo + kvbase);
#pragma unroll
        for (int j = 0; j < 4; j++) {
            int e = j * NTHREADS + tid;
            int row = e >> 3, c16 = e & 7;
            uint32_t srcb = (uint32_t)(row * 128 + c16 * 16);
            uint32_t dst  = swa(row, c16);
            CP_ASYNC16(sb + SM_KB0 + dst,        khi_p + srcb);
            CP_ASYNC16(sb + SM_KB0 + 8192 + dst, klo_p + srcb);
        }
        CP_COMMIT();
    }

    // ---- Prologue: stage Q (64x64 f32 -> bf16 hi/lo) into Kb1 region ----
    {
        const float* qp = q + ((size_t)b * SEQ + qbase) * DIM;
#pragma unroll
        for (int i = 0; i < (QT * DIM / 4) / NTHREADS; i++) {   // 8 iters
            int idx = i * NTHREADS + tid;
            int row = idx >> 4, f4 = idx & 15;
            float4 x = reinterpret_cast<const float4*>(qp + row * DIM)[f4];
            uint32_t off = swa(row, f4 >> 1) + (f4 & 1) * 8;
            *reinterpret_cast<uint2*>(smem + SM_KB1 + off) =
                make_uint2(packhi(x.x, x.y), packhi(x.z, x.w));
            *reinterpret_cast<uint2*>(smem + SM_KB1 + 8192 + off) =
                make_uint2(packlo(x.x, x.y), packlo(x.z, x.w));
        }
    }
    __syncthreads();

    // Q fragments (A of m16n8k16): 4 k-chunks of 16, hi and lo
    uint32_t qh[4][4], ql[4][4];
    {
        int arow = wr0 + (lane & 7) + ((lane >> 3) & 1) * 8;
#pragma unroll
        for (int kc = 0; kc < 4; kc++) {
            uint32_t off = swa(arow, kc * 2 + (lane >> 4));
            LDSM_X4(qh[kc][0], qh[kc][1], qh[kc][2], qh[kc][3], sb + SM_KB1 + off);
            LDSM_X4(ql[kc][0], ql[kc][1], ql[kc][2], ql[kc][3], sb + SM_KB1 + 8192 + off);
        }
    }
    __syncthreads();   // Kb1 free for K(1) prefetch after this

    float oacc[8][4];
#pragma unroll
    for (int nt = 0; nt < 8; nt++)
#pragma unroll
        for (int i = 0; i < 4; i++) oacc[nt][i] = 0.0f;
    // ones-MMA row-sum accumulator: every column = full row sum
    float lsacc[4] = {0.0f, 0.0f, 0.0f, 0.0f};
    const uint32_t ONES = 0x3F803F80u;   // bf16x2 {1.0, 1.0}

    const int m8 = lane >> 3;     // x4 ldmatrix operand selector
    const int r8 = lane & 7;

    for (int t = 0; t < NTILES; t++) {
        const uint32_t kbuf = sb + (uint32_t)(t & 1) * 16384;

        // ---- top commits: V(t) -> Vb, then K(t+1) -> other K buffer ----
        {
            const char* vhi_p = (const char*)(g_vhi + kvbase + (size_t)t * KT * DIM);
            const char* vlo_p = (const char*)(g_vlo + kvbase + (size_t)t * KT * DIM);
#pragma unroll
            for (int j = 0; j < 4; j++) {
                int e = j * NTHREADS + tid;
                int row = e >> 3, c16 = e & 7;
                uint32_t srcb = (uint32_t)(row * 128 + c16 * 16);
                uint32_t dst  = swa(row, c16);
                CP_ASYNC16(sb + SM_VB + dst,        vhi_p + srcb);
                CP_ASYNC16(sb + SM_VB + 8192 + dst, vlo_p + srcb);
            }
            CP_COMMIT();
        }
        const bool havenext = (t + 1 < NTILES);
        if (havenext) {
            const uint32_t nkb = sb + (uint32_t)((t + 1) & 1) * 16384;
            const char* khi_p = (const char*)(g_khi + kvbase + (size_t)(t + 1) * KT * DIM);
            const char* klo_p = (const char*)(g_klo + kvbase + (size_t)(t + 1) * KT * DIM);
#pragma unroll
            for (int j = 0; j < 4; j++) {
                int e = j * NTHREADS + tid;
                int row = e >> 3, c16 = e & 7;
                uint32_t srcb = (uint32_t)(row * 128 + c16 * 16);
                uint32_t dst  = swa(row, c16);
                CP_ASYNC16(nkb + dst,        khi_p + srcb);
                CP_ASYNC16(nkb + 8192 + dst, klo_p + srcb);
            }
            CP_COMMIT();
        }

        // ---- wait K(t) ready (keep V(t) [+ K(t+1)] in flight) ----
        if (havenext) { CP_WAITG(2); } else { CP_WAITG(1); }
        __syncthreads();

        // ---- per key-half: MMA1 -> exp -> (V-wait on first half) -> MMA2 ---
#pragma unroll
        for (int half = 0; half < 2; half++) {
            float sacc[4][4];
#pragma unroll
            for (int nt = 0; nt < 4; nt++)
#pragma unroll
                for (int i = 0; i < 4; i++) sacc[nt][i] = 0.0f;

            // MMA1: S(half) = Qhi.Khi^T + Qhi.Klo^T + Qlo.Khi^T
#pragma unroll
            for (int kc = 0; kc < 4; kc++) {
#pragma unroll
                for (int ntl = 0; ntl < 2; ntl++) {
                    int ntp = half * 2 + ntl;
                    int krow  = (ntp * 2 + (m8 >> 1)) * 8 + r8;
                    uint32_t off = swa(krow, kc * 2 + (m8 & 1));
                    uint32_t bh0, bh1, bh2, bh3, bl0, bl1, bl2, bl3;
                    LDSM_X4(bh0, bh1, bh2, bh3, kbuf + off);
                    LDSM_X4(bl0, bl1, bl2, bl3, kbuf + 8192 + off);
                    MMA(sacc[2*ntl],   qh[kc], bh0, bh1);
                    MMA(sacc[2*ntl+1], qh[kc], bh2, bh3);
                    MMA(sacc[2*ntl],   qh[kc], bl0, bl1);
                    MMA(sacc[2*ntl+1], qh[kc], bl2, bl3);
                    MMA(sacc[2*ntl],   ql[kc], bh0, bh1);
                    MMA(sacc[2*ntl+1], ql[kc], bh2, bh3);
                }
            }

            // exp(S) -> rn bf16 Phi fragments
            uint32_t ph[2][4];
#pragma unroll
            for (int ntl = 0; ntl < 4; ntl++) {
                float p0 = ex2f(sacc[ntl][0]);
                float p1 = ex2f(sacc[ntl][1]);
                float p2 = ex2f(sacc[ntl][2]);
                float p3 = ex2f(sacc[ntl][3]);
                int kcl = ntl >> 1, h = (ntl & 1) * 2;
                ph[kcl][h]     = packhi(p0, p1);
                ph[kcl][h + 1] = packhi(p2, p3);
            }

            // first half: make sure V(t) has landed (K(t+1) may stay in flight)
            if (half == 0) {
                if (havenext) { CP_WAITG(1); } else { CP_WAITG(0); }
                __syncthreads();
            }

            // MMA2: O += Phi.Vhi + Phi.Vlo ; ones-MMA row sums
#pragma unroll
            for (int kcl = 0; kcl < 2; kcl++) {
                int kcg = half * 2 + kcl;
                MMA(lsacc, ph[kcl], ONES, ONES);
#pragma unroll
                for (int ntp = 0; ntp < 4; ntp++) {
                    int vrow = kcg * 16 + (m8 & 1) * 8 + r8;
                    uint32_t off = swa(vrow, ntp * 2 + (m8 >> 1));
                    uint32_t bh0, bh1, bh2, bh3, bl0, bl1, bl2, bl3;
                    LDSM_X4T(bh0, bh1, bh2, bh3, sb + SM_VB + off);
                    LDSM_X4T(bl0, bl1, bl2, bl3, sb + SM_VB + 8192 + off);
                    MMA(oacc[2*ntp],   ph[kcl], bh0, bh1);
                    MMA(oacc[2*ntp+1], ph[kcl], bh2, bh3);
                    MMA(oacc[2*ntp],   ph[kcl], bl0, bl1);
                    MMA(oacc[2*ntp+1], ph[kcl], bl2, bl3);
                }
            }
        }
        __syncthreads();   // K reads (MMA1 h1) + V reads (MMA2 h1) done
    }

    // ---- row sums complete per-lane (ones-MMA) -> no cross-lane reduction --
    const float inv0 = 1.0f / lsacc[0];
    const float inv1 = 1.0f / lsacc[2];

    // ---- normalize + store ----
    {
        const int r = lane >> 2, c = lane & 3;
        float* op0 = out + ((size_t)b * SEQ + qbase + wr0 + r) * DIM;
        float* op1 = op0 + 8 * DIM;
#pragma unroll
        for (int nt = 0; nt < 8; nt++) {
            float2 t0 = make_float2(oacc[nt][0] * inv0, oacc[nt][1] * inv0);
            float2 t1 = make_float2(oacc[nt][2] * inv1, oacc[nt][3] * inv1);
            *reinterpret_cast<float2*>(op0 + nt * 8 + 2 * c) = t0;
            *reinterpret_cast<float2*>(op1 + nt * 8 + 2 * c) = t1;
        }
    }
}

extern "C" void kernel_launch(void* const* d_in, const int* in_sizes, int n_in,
                              void* d_out, int out_size)
{
    const float* q = (const float*)d_in[0];
    const float* k = (const float*)d_in[1];
    const float* v = (const float*)d_in[2];
    float* out = (float*)d_out;

    kv_convert_kernel<<<KV_ELEMS / 4 / 256, 256>>>(k, v);

    dim3 grid(SEQ / QT, BATCH);
    attn_mma_kernel<<<grid, NTHREADS>>>(q, out);
}

// round 17
// speedup vs baseline: 1.0409x; 1.0409x over previous
#include <cuda_runtime.h>
#include <cuda_bf16.h>
#include <cstdint>

// ============================================================================
// multimodal_attention via mma.sync (HMMA bf16 hi/lo split) on sm_103
// out[b,q,:] = softmax_k(Q.K^T) @ V       B=32, S=2048, D=64, fp32
//
// R16: 4 CTAs/SM via KT=32 (full double-buffering at 32KB/CTA, R13's exact
//      2-sync pipeline preserved; no mid-tile V wait).  Per-warp state ~120
//      regs fits the 128-reg/4-CTA cap.  Scratch arrays consolidated.
// ============================================================================

#define BATCH 32
#define SEQ   2048
#define DIM   64
#define QT    64             // q rows per CTA
#define KT    32             // keys per tile
#define NTILES (SEQ / KT)    // 64
#define NTHREADS 128

#define KV_ELEMS (BATCH * SEQ * DIM)     // 4,194,304

// preconverted K/V scratch: [0]=khi [1]=klo [2]=vhi [3]=vlo (K scaled log2e)
__device__ __nv_bfloat16 g_kv[4][KV_ELEMS];

// smem: double buffer, each buf = {KHI,KLO,VHI,VLO} 4KB tiles = 16KB
#define BUF_STRIDE 16384
#define T_KHI 0
#define T_KLO 4096
#define T_VHI 8192
#define T_VLO 12288
#define SMEM_BYTES (2 * BUF_STRIDE)      // 32KB static

__device__ __forceinline__ uint32_t smem_u32(const void* p) {
    uint32_t a;
    asm("{ .reg .u64 t; cvta.to.shared.u64 t, %1; cvt.u32.u64 %0, t; }" : "=r"(a) : "l"(p));
    return a;
}
// 128B rows; xor-swizzle 16B chunks by row&7 -> conflict-free ldmatrix
__device__ __forceinline__ uint32_t swa(int row, int col16) {
    return (uint32_t)(row * 128 + ((col16 ^ (row & 7)) << 4));
}
__device__ __forceinline__ uint32_t packhi(float a, float b) {
    __nv_bfloat162 t = __floats2bfloat162_rn(a, b);
    return *reinterpret_cast<uint32_t*>(&t);
}
__device__ __forceinline__ uint32_t packlo(float a, float b) {
    float ah = __bfloat162float(__float2bfloat16_rn(a));
    float bh = __bfloat162float(__float2bfloat16_rn(b));
    __nv_bfloat162 t = __floats2bfloat162_rn(a - ah, b - bh);
    return *reinterpret_cast<uint32_t*>(&t);
}
__device__ __forceinline__ float ex2f(float x) {
    float r;
    asm("ex2.approx.ftz.f32 %0, %1;" : "=f"(r) : "f"(x));
    return r;
}

#define CP_ASYNC16(SM, GM) \
    asm volatile("cp.async.cg.shared.global [%0], [%1], 16;" :: "r"(SM), "l"(GM) : "memory")
#define CP_COMMIT()  asm volatile("cp.async.commit_group;" ::: "memory")
#define CP_WAIT0()   asm volatile("cp.async.wait_group 0;" ::: "memory")
#define CP_WAIT1()   asm volatile("cp.async.wait_group 1;" ::: "memory")

#define LDSM_X4(R0,R1,R2,R3,ADDR) \
    asm volatile("ldmatrix.sync.aligned.m8n8.x4.shared.b16 {%0,%1,%2,%3}, [%4];" \
                 : "=r"(R0),"=r"(R1),"=r"(R2),"=r"(R3) : "r"(ADDR))
#define LDSM_X4T(R0,R1,R2,R3,ADDR) \
    asm volatile("ldmatrix.sync.aligned.m8n8.x4.trans.shared.b16 {%0,%1,%2,%3}, [%4];" \
                 : "=r"(R0),"=r"(R1),"=r"(R2),"=r"(R3) : "r"(ADDR))
// D += A * B   (m16n8k16, bf16 in, f32 accum)
#define MMA(D,A,B0,B1) \
    asm volatile("mma.sync.aligned.m16n8k16.row.col.f32.bf16.bf16.f32 " \
                 "{%0,%1,%2,%3},{%4,%5,%6,%7},{%8,%9},{%0,%1,%2,%3};" \
                 : "+f"((D)[0]),"+f"((D)[1]),"+f"((D)[2]),"+f"((D)[3]) \
                 : "r"((A)[0]),"r"((A)[1]),"r"((A)[2]),"r"((A)[3]),"r"(B0),"r"(B1))

// ---------------------------------------------------------------------------
// Pre-pass: K,V fp32 -> bf16 hi/lo scratch.  K scaled by log2(e).
// ---------------------------------------------------------------------------
__global__ __launch_bounds__(256)
void kv_convert_kernel(const float* __restrict__ k, const float* __restrict__ v)
{
    const float LOG2E = 1.4426950408889634f;
    int i = blockIdx.x * 256 + threadIdx.x;          // float4 index
    float4 kx = reinterpret_cast<const float4*>(k)[i];
    kx.x *= LOG2E; kx.y *= LOG2E; kx.z *= LOG2E; kx.w *= LOG2E;
    float4 vx = reinterpret_cast<const float4*>(v)[i];
    reinterpret_cast<uint2*>(g_kv[0])[i] = make_uint2(packhi(kx.x, kx.y), packhi(kx.z, kx.w));
    reinterpret_cast<uint2*>(g_kv[1])[i] = make_uint2(packlo(kx.x, kx.y), packlo(kx.z, kx.w));
    reinterpret_cast<uint2*>(g_kv[2])[i] = make_uint2(packhi(vx.x, vx.y), packhi(vx.z, vx.w));
    reinterpret_cast<uint2*>(g_kv[3])[i] = make_uint2(packlo(vx.x, vx.y), packlo(vx.z, vx.w));
}

// ---------------------------------------------------------------------------
// Attention kernel
// ---------------------------------------------------------------------------
__global__ __launch_bounds__(NTHREADS, 4)
void attn_mma_kernel(const float* __restrict__ q,
                     float* __restrict__ out)
{
    __shared__ __align__(1024) char smem[SMEM_BYTES];
    const uint32_t sb = smem_u32(smem);
    const int tid  = threadIdx.x;
    const int w    = tid >> 5;                // warp 0..3
    const int lane = tid & 31;
    const int b     = blockIdx.y;
    const int qbase = blockIdx.x * QT;
    const int wr0   = w * 16;                 // this warp's q-row base in tile

    const size_t kvbase = (size_t)b * SEQ * DIM;

    // per-tile staging: 4 arrays x 4KB; 8 cp.async16 per thread.
    // i 0..7: arr = i>>1, e = (i&1)*128 + tid, row = e>>3 (0..31), c16 = e&7.

    // ---- kick off DMA of tile 0 into buf0 ----
    {
#pragma unroll
        for (int i = 0; i < 8; i++) {
            int arr = i >> 1, e = (i & 1) * NTHREADS + tid;
            int row = e >> 3, c16 = e & 7;
            const char* src = (const char*)(g_kv[arr] + kvbase) + row * 128 + c16 * 16;
            CP_ASYNC16(sb + arr * 4096 + swa(row, c16), src);
        }
        CP_COMMIT();
    }

    // ---- Prologue: stage Q (64x64 f32 -> bf16 hi/lo) into buf1 (16KB) ----
    {
        const float* qp = q + ((size_t)b * SEQ + qbase) * DIM;
#pragma unroll
        for (int i = 0; i < (QT * DIM / 4) / NTHREADS; i++) {   // 8 iters
            int idx = i * NTHREADS + tid;
            int row = idx >> 4, f4 = idx & 15;
            float4 x = reinterpret_cast<const float4*>(qp + row * DIM)[f4];
            uint32_t off = swa(row, f4 >> 1) + (f4 & 1) * 8;
            *reinterpret_cast<uint2*>(smem + BUF_STRIDE + off) =
                make_uint2(packhi(x.x, x.y), packhi(x.z, x.w));
            *reinterpret_cast<uint2*>(smem + BUF_STRIDE + 8192 + off) =
                make_uint2(packlo(x.x, x.y), packlo(x.z, x.w));
        }
    }
    __syncthreads();

    // Q fragments (A of m16n8k16): 4 k-chunks of 16, hi and lo
    uint32_t qh[4][4], ql[4][4];
    {
        int arow = wr0 + (lane & 7) + ((lane >> 3) & 1) * 8;
#pragma unroll
        for (int kc = 0; kc < 4; kc++) {
            uint32_t off = swa(arow, kc * 2 + (lane >> 4));
            LDSM_X4(qh[kc][0], qh[kc][1], qh[kc][2], qh[kc][3], sb + BUF_STRIDE + off);
            LDSM_X4(ql[kc][0], ql[kc][1], ql[kc][2], ql[kc][3], sb + BUF_STRIDE + 8192 + off);
        }
    }
    __syncthreads();   // buf1 free for tile-1 prefetch after this

    float oacc[8][4];
#pragma unroll
    for (int nt = 0; nt < 8; nt++)
#pragma unroll
        for (int i = 0; i < 4; i++) oacc[nt][i] = 0.0f;
    // ones-MMA row-sum accumulator: every column = full row sum
    float lsacc[4] = {0.0f, 0.0f, 0.0f, 0.0f};
    const uint32_t ONES = 0x3F803F80u;   // bf16x2 {1.0, 1.0}

    const int m8 = lane >> 3;     // x4 ldmatrix operand selector
    const int r8 = lane & 7;

    for (int t = 0; t < NTILES; t++) {
        const uint32_t bufb = sb + (uint32_t)(t & 1) * BUF_STRIDE;

        // ---- prefetch tile t+1 into the other buffer; wait for tile t ----
        if (t + 1 < NTILES) {
            const size_t toff = kvbase + (size_t)(t + 1) * KT * DIM;
            const uint32_t nb = sb + (uint32_t)((t + 1) & 1) * BUF_STRIDE;
#pragma unroll
            for (int i = 0; i < 8; i++) {
                int arr = i >> 1, e = (i & 1) * NTHREADS + tid;
                int row = e >> 3, c16 = e & 7;
                const char* src = (const char*)(g_kv[arr] + toff) + row * 128 + c16 * 16;
                CP_ASYNC16(nb + arr * 4096 + swa(row, c16), src);
            }
            CP_COMMIT();
            CP_WAIT1();          // oldest group (tile t) complete
        } else {
            CP_WAIT0();
        }
        __syncthreads();

        // ---- MMA1: S[16,32] = Qhi.Khi^T + Qhi.Klo^T + Qlo.Khi^T ----
        float sacc[4][4];
#pragma unroll
        for (int nt = 0; nt < 4; nt++)
#pragma unroll
            for (int i = 0; i < 4; i++) sacc[nt][i] = 0.0f;

#pragma unroll
        for (int kc = 0; kc < 4; kc++) {
#pragma unroll
            for (int ntp = 0; ntp < 2; ntp++) {
                int krow  = (ntp * 2 + (m8 >> 1)) * 8 + r8;
                uint32_t off = swa(krow, kc * 2 + (m8 & 1));
                uint32_t bh0, bh1, bh2, bh3, bl0, bl1, bl2, bl3;
                LDSM_X4(bh0, bh1, bh2, bh3, bufb + T_KHI + off);
                LDSM_X4(bl0, bl1, bl2, bl3, bufb + T_KLO + off);
                MMA(sacc[2*ntp],   qh[kc], bh0, bh1);
                MMA(sacc[2*ntp+1], qh[kc], bh2, bh3);
                MMA(sacc[2*ntp],   qh[kc], bl0, bl1);
                MMA(sacc[2*ntp+1], qh[kc], bl2, bl3);
                MMA(sacc[2*ntp],   ql[kc], bh0, bh1);
                MMA(sacc[2*ntp+1], ql[kc], bh2, bh3);
            }
        }

        // ---- exp(S) -> rn bf16 Phi fragments ----
        uint32_t ph[2][4];
#pragma unroll
        for (int nt = 0; nt < 4; nt++) {
            float p0 = ex2f(sacc[nt][0]);
            float p1 = ex2f(sacc[nt][1]);
            float p2 = ex2f(sacc[nt][2]);
            float p3 = ex2f(sacc[nt][3]);
            int kcl = nt >> 1, h = (nt & 1) * 2;
            ph[kcl][h]     = packhi(p0, p1);
            ph[kcl][h + 1] = packhi(p2, p3);
        }

        // ---- MMA2: O += Phi.Vhi + Phi.Vlo ; ones-MMA row sums ----
#pragma unroll
        for (int kcl = 0; kcl < 2; kcl++) {
            MMA(lsacc, ph[kcl], ONES, ONES);
#pragma unroll
            for (int ntp = 0; ntp < 4; ntp++) {
                int vrow = kcl * 16 + (m8 & 1) * 8 + r8;
                uint32_t off = swa(vrow, ntp * 2 + (m8 >> 1));
                uint32_t bh0, bh1, bh2, bh3, bl0, bl1, bl2, bl3;
                LDSM_X4T(bh0, bh1, bh2, bh3, bufb + T_VHI + off);
                LDSM_X4T(bl0, bl1, bl2, bl3, bufb + T_VLO + off);
                MMA(oacc[2*ntp],   ph[kcl], bh0, bh1);
                MMA(oacc[2*ntp+1], ph[kcl], bh2, bh3);
                MMA(oacc[2*ntp],   ph[kcl], bl0, bl1);
                MMA(oacc[2*ntp+1], ph[kcl], bl2, bl3);
            }
        }
        __syncthreads();   // tile t reads done -> buffer reusable next iter
    }

    // ---- row sums complete per-lane (ones-MMA) -> no cross-lane reduction --
    const float inv0 = 1.0f / lsacc[0];
    const float inv1 = 1.0f / lsacc[2];

    // ---- normalize + store ----
    {
        const int r = lane >> 2, c = lane & 3;
        float* op0 = out + ((size_t)b * SEQ + qbase + wr0 + r) * DIM;
        float* op1 = op0 + 8 * DIM;
#pragma unroll
        for (int nt = 0; nt < 8; nt++) {
            float2 t0 = make_float2(oacc[nt][0] * inv0, oacc[nt][1] * inv0);
            float2 t1 = make_float2(oacc[nt][2] * inv1, oacc[nt][3] * inv1);
            *reinterpret_cast<float2*>(op0 + nt * 8 + 2 * c) = t0;
            *reinterpret_cast<float2*>(op1 + nt * 8 + 2 * c) = t1;
        }
    }
}

extern "C" void kernel_launch(void* const* d_in, const int* in_sizes, int n_in,
                              void* d_out, int out_size)
{
    const float* q = (const float*)d_in[0];
    const float* k = (const float*)d_in[1];
    const float* v = (const float*)d_in[2];
    float* out = (float*)d_out;

    kv_convert_kernel<<<KV_ELEMS / 4 / 256, 256>>>(k, v);

    dim3 grid(SEQ / QT, BATCH);
    attn_mma_kernel<<<grid, NTHREADS>>>(q, out);
}